// round 16
// baseline (speedup 1.0000x reference)
#include <cuda_runtime.h>
#include <cuda_bf16.h>
#include <math.h>
#include <stdint.h>

#define B_MAX 2048
// IN_N=50 OUT_N=10 KER=10 FEAT=66 HID=256 VLEN=20 VSEQ=31 IF=40 NBLK=12

__device__ float g_ginp[B_MAX * 66 * 40];
__device__ float g_buf0[B_MAX * 66 * 256];
__device__ float g_w1qT[416 * 256];
__device__ float g_w2qT[1280 * 256];
__device__ float g_w1kT[416 * 256];
__device__ float g_w2kT[1280 * 256];
__device__ float g_dct [400];
__device__ __nv_bfloat16 g_whi[13 * 65536];
__device__ __nv_bfloat16 g_wlo[13 * 65536];
__device__ __nv_bfloat16 g_ahi[13 * 7040];   // [80 rows][88 cols]
__device__ __nv_bfloat16 g_alo[13 * 7040];

// ---- packed f32x2 helpers (SASS FFMA2) ----
__device__ __forceinline__ void fma2(unsigned long long& c, unsigned long long a,
                                     unsigned long long b) {
    asm("fma.rn.f32x2 %0, %1, %2, %0;" : "+l"(c) : "l"(a), "l"(b));
}
__device__ __forceinline__ unsigned long long pack2(float x, float y) {
    unsigned long long r;
    asm("mov.b64 %0, {%1, %2};" : "=l"(r) : "f"(x), "f"(y));
    return r;
}
__device__ __forceinline__ float2 unpack2(unsigned long long v) {
    float2 r;
    asm("mov.b64 {%0, %1}, %2;" : "=f"(r.x), "=f"(r.y) : "l"(v));
    return r;
}

// ---- mma.sync helpers ----
__device__ __forceinline__ uint32_t smem_u32(const void* p) {
    uint32_t a;
    asm("{ .reg .u64 t; cvta.to.shared.u64 t, %1; cvt.u32.u64 %0, t; }"
        : "=r"(a) : "l"(p));
    return a;
}
__device__ __forceinline__ void ldsm4(uint32_t* r, uint32_t addr) {
    asm volatile("ldmatrix.sync.aligned.m8n8.x4.shared.b16 {%0,%1,%2,%3}, [%4];"
                 : "=r"(r[0]), "=r"(r[1]), "=r"(r[2]), "=r"(r[3]) : "r"(addr));
}
__device__ __forceinline__ void mma16816(float* d, const uint32_t* a, const uint32_t* b) {
    asm volatile(
        "mma.sync.aligned.m16n8k16.row.col.f32.bf16.bf16.f32 "
        "{%0,%1,%2,%3}, {%4,%5,%6,%7}, {%8,%9}, {%0,%1,%2,%3};"
        : "+f"(d[0]), "+f"(d[1]), "+f"(d[2]), "+f"(d[3])
        : "r"(a[0]), "r"(a[1]), "r"(a[2]), "r"(a[3]), "r"(b[0]), "r"(b[1]));
}

// ---- all setup in one kernel ----
__global__ void k_prep(const float* __restrict__ q_w1, const float* __restrict__ k_w1,
                       const float* __restrict__ q_w2, const float* __restrict__ k_w2,
                       const float* __restrict__ gin_w, const float* __restrict__ blk_w,
                       const float* __restrict__ gin_att, const float* __restrict__ blk_att)
{
    int gid = blockIdx.x * blockDim.x + threadIdx.x;
    int GS = gridDim.x * blockDim.x;
    for (int t = gid; t < 400; t += GS) {
        int k = t / 20, i = t % 20;
        float w = (k == 0) ? sqrtf(1.0f / 20.0f) : sqrtf(2.0f / 20.0f);
        g_dct[t] = w * cospif((i + 0.5f) * (float)k / 20.0f);
    }
    for (int i = gid; i < 416 * 256; i += GS) {
        int k = i >> 8, h = i & 255;
        float vq = 0.0f, vk = 0.0f;
        if (k < 396) {
            int l = k / 66, f = k - l * 66;
            vq = q_w1[h * 396 + f * 6 + l];
            vk = k_w1[h * 396 + f * 6 + l];
        }
        g_w1qT[i] = vq; g_w1kT[i] = vk;
    }
    for (int i = gid; i < 1280 * 256; i += GS) {
        int k = i >> 8, h = i & 255, l = k >> 8, c = k & 255;
        g_w2qT[i] = q_w2[h * 1280 + c * 5 + l];
        g_w2kT[i] = k_w2[h * 1280 + c * 5 + l];
    }
    for (int idx = gid; idx < 13 * 65536; idx += GS) {
        int l = idx >> 16, r = idx & 65535;
        int kc = r >> 14, rem = r & 16383;
        int n = rem >> 6, kk = rem & 63;
        int k = kc * 64 + kk;
        float a;
        if (l == 0) a = (k < 40) ? gin_w[k * 256 + n] : 0.0f;
        else        a = blk_w[(size_t)(l - 1) * 65536 + k * 256 + n];
        __nv_bfloat16 h = __float2bfloat16(a);
        g_whi[idx] = h;
        g_wlo[idx] = __float2bfloat16(a - __bfloat162float(h));
    }
    for (int idx = gid; idx < 13 * 7040; idx += GS) {
        int l = idx / 7040, r = idx - l * 7040;
        int n = r / 88, m = r - n * 88;
        float a = 0.0f;
        if (n < 66 && m < 66)
            a = (l == 0) ? gin_att[n * 66 + m]
                         : blk_att[(size_t)(l - 1) * 4356 + n * 66 + m];
        __nv_bfloat16 h = __float2bfloat16(a);
        g_ahi[idx] = h;
        g_alo[idx] = __float2bfloat16(a - __bfloat162float(h));
    }
}

// ---- mega front-end (unchanged) ----
#define FS_H1   3776
#define FS_WTK  14176
#define FS_WTQ  22368
#define FS_OUT2 30560
#define SM_F    (38784 * 4)
__global__ __launch_bounds__(512, 1) void k_front(
    const float* __restrict__ x,
    const float* __restrict__ b1q, const float* __restrict__ b1k,
    const float* __restrict__ b2q, const float* __restrict__ b2k,
    float* __restrict__ ginp)
{
    extern __shared__ float sm[];
    float* xs = sm;
    float* ds = sm + 3300;
    float* sc = sm + 3700;
    float* asw = sm + 3732;
    float* h1 = sm + FS_H1;
    float* wtk = sm + FS_WTK;
    float* wtq = sm + FS_WTQ;
    float* out2 = sm + FS_OUT2;
    const int t = threadIdx.x, b = blockIdx.x;
    const int wid = t >> 5, lane = t & 31;
    const int mg = t & 7, h0 = (t >> 3) * 4;

    for (int i = t; i < 3300; i += 512) xs[i] = x[(size_t)b * 3300 + i];
    for (int i = t; i < 400; i += 512) ds[i] = g_dct[i];

    {   // conv1 q (5 rows)
        unsigned long long acc[2] = {0ULL, 0ULL};
        for (int nt = 0; nt < 13; nt++) {
            __syncthreads();
            for (int i = t; i < 8192; i += 512) wtk[i] = g_w1qT[nt * 8192 + i];
            __syncthreads();
#pragma unroll 4
            for (int kk = 0; kk < 32; kk++) {
                int kc = min(nt * 32 + kk, 395);
                int l = kc / 66, c = kc - l * 66;
                float4 w4 = *(const float4*)&wtk[kk * 256 + h0];
                unsigned long long wlo = pack2(w4.x, w4.y), whi = pack2(w4.z, w4.w);
                if (mg < 5) {
                    float y = xs[(40 + mg + l) * 66 + c];
                    unsigned long long yy = pack2(y, y);
                    fma2(acc[0], yy, wlo);
                    fma2(acc[1], yy, whi);
                }
            }
        }
        if (mg < 5) {
            float4 bv = *(const float4*)&b1q[h0];
            float2 lo = unpack2(acc[0]), hi = unpack2(acc[1]);
            float* hr = &h1[mg * 260 + h0];
            hr[0] = fmaxf(lo.x + bv.x, 0.0f); hr[1] = fmaxf(lo.y + bv.y, 0.0f);
            hr[2] = fmaxf(hi.x + bv.z, 0.0f); hr[3] = fmaxf(hi.y + bv.w, 0.0f);
        }
    }
    {   // conv1 k (35 rows -> h1 rows 5..39)
        unsigned long long acc[5][2];
#pragma unroll
        for (int i = 0; i < 5; i++) { acc[i][0] = 0ULL; acc[i][1] = 0ULL; }
        for (int nt = 0; nt < 13; nt++) {
            __syncthreads();
            for (int i = t; i < 8192; i += 512) wtk[i] = g_w1kT[nt * 8192 + i];
            __syncthreads();
#pragma unroll 4
            for (int kk = 0; kk < 32; kk++) {
                int kc = min(nt * 32 + kk, 395);
                int l = kc / 66, c = kc - l * 66;
                float4 w4 = *(const float4*)&wtk[kk * 256 + h0];
                unsigned long long wlo = pack2(w4.x, w4.y), whi = pack2(w4.z, w4.w);
#pragma unroll
                for (int i = 0; i < 5; i++) {
                    int p = mg + 8 * i;
                    if (p < 35) {
                        float y = xs[(p + l) * 66 + c];
                        unsigned long long yy = pack2(y, y);
                        fma2(acc[i][0], yy, wlo);
                        fma2(acc[i][1], yy, whi);
                    }
                }
            }
        }
        float4 bv = *(const float4*)&b1k[h0];
#pragma unroll
        for (int i = 0; i < 5; i++) {
            int p = mg + 8 * i;
            if (p < 35) {
                float2 lo = unpack2(acc[i][0]), hi = unpack2(acc[i][1]);
                float* hr = &h1[(5 + p) * 260 + h0];
                hr[0] = fmaxf(lo.x + bv.x, 0.0f); hr[1] = fmaxf(lo.y + bv.y, 0.0f);
                hr[2] = fmaxf(hi.x + bv.z, 0.0f); hr[3] = fmaxf(hi.y + bv.w, 0.0f);
            }
        }
    }
    {   // conv2 (q row 0, k rows 1..31 of out2)
        unsigned long long acck[4][2], accq[2] = {0ULL, 0ULL};
#pragma unroll
        for (int i = 0; i < 4; i++) { acck[i][0] = 0ULL; acck[i][1] = 0ULL; }
        for (int nt = 0; nt < 40; nt++) {
            __syncthreads();
            for (int i = t; i < 8192; i += 512) {
                wtk[i] = g_w2kT[nt * 8192 + i];
                wtq[i] = g_w2qT[nt * 8192 + i];
            }
            __syncthreads();
#pragma unroll 4
            for (int kk = 0; kk < 32; kk++) {
                int kc = nt * 32 + kk;
                int l = kc >> 8, c = kc & 255;
                float4 w4 = *(const float4*)&wtk[kk * 256 + h0];
                unsigned long long wlo = pack2(w4.x, w4.y), whi = pack2(w4.z, w4.w);
#pragma unroll
                for (int i = 0; i < 4; i++) {
                    int s = mg + 8 * i;
                    if (s < 31) {
                        float y = h1[(5 + s + l) * 260 + c];
                        unsigned long long yy = pack2(y, y);
                        fma2(acck[i][0], yy, wlo);
                        fma2(acck[i][1], yy, whi);
                    }
                }
                if (mg == 0) {
                    float4 wq = *(const float4*)&wtq[kk * 256 + h0];
                    float y = h1[l * 260 + c];
                    unsigned long long yy = pack2(y, y);
                    fma2(accq[0], yy, pack2(wq.x, wq.y));
                    fma2(accq[1], yy, pack2(wq.z, wq.w));
                }
            }
        }
        float4 bv = *(const float4*)&b2k[h0];
#pragma unroll
        for (int i = 0; i < 4; i++) {
            int s = mg + 8 * i;
            if (s < 31) {
                float2 lo = unpack2(acck[i][0]), hi = unpack2(acck[i][1]);
                float* orow = &out2[(1 + s) * 257 + h0];
                orow[0] = fmaxf(lo.x + bv.x, 0.0f); orow[1] = fmaxf(lo.y + bv.y, 0.0f);
                orow[2] = fmaxf(hi.x + bv.z, 0.0f); orow[3] = fmaxf(hi.y + bv.w, 0.0f);
            }
        }
        if (mg == 0) {
            float4 bq = *(const float4*)&b2q[h0];
            float2 lo = unpack2(accq[0]), hi = unpack2(accq[1]);
            float* orow = &out2[h0];
            orow[0] = fmaxf(lo.x + bq.x, 0.0f); orow[1] = fmaxf(lo.y + bq.y, 0.0f);
            orow[2] = fmaxf(hi.x + bq.z, 0.0f); orow[3] = fmaxf(hi.y + bq.w, 0.0f);
        }
    }
    __syncthreads();
    for (int s = wid; s < 31; s += 16) {
        float v = 0.0f;
        for (int j = lane; j < 256; j += 32) v += out2[j] * out2[(1 + s) * 257 + j];
#pragma unroll
        for (int o = 16; o; o >>= 1) v += __shfl_down_sync(0xffffffffu, v, o);
        if (!lane) sc[s] = v;
    }
    __syncthreads();
    if (t < 32) {
        float v = (t < 31) ? sc[t] : 0.0f, tot = v;
#pragma unroll
        for (int o = 16; o; o >>= 1) tot += __shfl_xor_sync(0xffffffffu, tot, o);
        if (t < 31) asw[t] = v / tot;
    }
    __syncthreads();
    if (t < 264) {
        int f2 = t >> 2, mq = t & 3;
        if (f2 < 66) {
            float G[20];
#pragma unroll
            for (int l = 0; l < 20; l++) G[l] = 0.0f;
            for (int s = 0; s < 31; s++) {
                int j = f2 * 31 + s, sj = j / 66, fj = j - sj * 66;
                float a = asw[s];
#pragma unroll
                for (int l = 0; l < 20; l++) G[l] += a * xs[(sj + l) * 66 + fj];
            }
            float xp[20];
#pragma unroll
            for (int l = 0; l < 20; l++) xp[l] = xs[((l < 10) ? (40 + l) : 49) * 66 + f2];
            float* ob = ginp + (size_t)b * 2640 + f2 * 40;
            for (int m = mq * 5; m < mq * 5 + 5; m++) {
                float pq = 0.0f, af = 0.0f;
#pragma unroll
                for (int l = 0; l < 20; l++) {
                    float d = ds[l * 20 + m];
                    pq += xp[l] * d; af += G[l] * d;
                }
                ob[m] = pq; ob[20 + m] = af;
            }
        }
    }
}

// ---- input layer (KD=40), M=80 asymmetric warp split ----
// smem: A@0(14080 hi)/@14080(lo) YT@28160(45056 hi)/@73216(lo) end 118272
//       U@0(42240 hi)/@42240(lo) (alias dead A+YT)  W@118272(hi)/@155136(lo)
//       bias@192000  SM_T=193024
#define SM_T 193024
__global__ __launch_bounds__(512, 1) void k_tlayer40(
    const float* __restrict__ Yin,
    const __nv_bfloat16* __restrict__ Whi, const __nv_bfloat16* __restrict__ Wlo,
    const __nv_bfloat16* __restrict__ Ahi, const __nv_bfloat16* __restrict__ Alo,
    const float* __restrict__ bias, const float* __restrict__ g,
    const float* __restrict__ be, float* __restrict__ Out)
{
    extern __shared__ float sm[];
    char* smc = (char*)sm;
    float* bs = (float*)(smc + 192000);
    const int t = threadIdx.x, b = blockIdx.x;
    const int wid = t >> 5, lid = t & 31;
    const int wm = wid >> 3, wn = wid & 7;
    const int nmi = 3 - wm;
    const uint32_t base = smem_u32(smc);
    const uint32_t uA_hi = base, uA_lo = base + 14080;
    const uint32_t uYT_hi = base + 28160, uYT_lo = base + 73216;
    const uint32_t uU_hi = base, uU_lo = base + 42240;
    const uint32_t uW_hi = base + 118272, uW_lo = base + 155136;

    if (t < 256) bs[t] = bias[t];
    {
        const uint4* sH = (const uint4*)Ahi;
        const uint4* sL = (const uint4*)Alo;
        for (int i = t; i < 880; i += 512) {
            ((uint4*)smc)[i] = sH[i];
            ((uint4*)(smc + 14080))[i] = sL[i];
        }
    }
    for (int i = t; i < 22528; i += 512) ((uint32_t*)(smc + 28160))[i] = 0;
    __syncthreads();
    for (int i = t; i < 66 * 40; i += 512) {
        int m = i / 40, j = i - m * 40;
        float a = Yin[(size_t)b * 2640 + i];
        __nv_bfloat16 h = __float2bfloat16(a);
        __nv_bfloat16 l = __float2bfloat16(a - __bfloat162float(h));
        *(__nv_bfloat16*)(smc + 28160 + j * 176 + m * 2) = h;
        *(__nv_bfloat16*)(smc + 73216 + j * 176 + m * 2) = l;
    }
    __syncthreads();

    float c[3][4][4];
#pragma unroll
    for (int mi = 0; mi < 3; mi++)
#pragma unroll
        for (int ni = 0; ni < 4; ni++)
#pragma unroll
            for (int j = 0; j < 4; j++) c[mi][ni][j] = 0.0f;

    if (wn < 2) {   // only U cols < 64 nonzero (KD=40)
#pragma unroll
        for (int s = 0; s < 5; s++) {
            uint32_t ah[3][4], al[3][4];
#pragma unroll
            for (int mi = 0; mi < 3; mi++) {
                if (mi >= nmi) continue;
                uint32_t off = (uint32_t)(wm * 48 + mi * 16 + (lid & 7) + ((lid >> 3) & 1) * 8) * 176
                             + s * 32 + ((lid >> 4) & 1) * 16;
                ldsm4(ah[mi], uA_hi + off);
                ldsm4(al[mi], uA_lo + off);
            }
#pragma unroll
            for (int np = 0; np < 2; np++) {
                uint32_t off = (uint32_t)(wn * 32 + np * 16 + (lid & 7) + ((lid >> 4) & 1) * 8) * 176
                             + s * 32 + ((lid >> 3) & 1) * 16;
                uint32_t bh[4], bl[4];
                ldsm4(bh, uYT_hi + off);
                ldsm4(bl, uYT_lo + off);
#pragma unroll
                for (int mi = 0; mi < 3; mi++) {
                    if (mi >= nmi) continue;
                    mma16816(c[mi][np * 2],     ah[mi], bh);
                    mma16816(c[mi][np * 2 + 1], ah[mi], bh + 2);
                    mma16816(c[mi][np * 2],     ah[mi], bl);
                    mma16816(c[mi][np * 2 + 1], ah[mi], bl + 2);
                    mma16816(c[mi][np * 2],     al[mi], bh);
                    mma16816(c[mi][np * 2 + 1], al[mi], bh + 2);
                }
            }
        }
    }
    __syncthreads();

#pragma unroll
    for (int mi = 0; mi < 3; mi++) {
        if (mi >= nmi) continue;
        int r0 = wm * 48 + mi * 16 + (lid >> 2);
#pragma unroll
        for (int ni = 0; ni < 4; ni++) {
            int cc = wn * 32 + ni * 8 + (lid & 3) * 2;
            float v0 = c[mi][ni][0], v1 = c[mi][ni][1];
            float v2 = c[mi][ni][2], v3 = c[mi][ni][3];
            __nv_bfloat162 h01 = __floats2bfloat162_rn(v0, v1);
            __nv_bfloat162 l01 = __floats2bfloat162_rn(v0 - __bfloat162float(h01.x),
                                                       v1 - __bfloat162float(h01.y));
            __nv_bfloat162 h23 = __floats2bfloat162_rn(v2, v3);
            __nv_bfloat162 l23 = __floats2bfloat162_rn(v2 - __bfloat162float(h23.x),
                                                       v3 - __bfloat162float(h23.y));
            *(__nv_bfloat162*)(smc + r0 * 528 + cc * 2) = h01;
            *(__nv_bfloat162*)(smc + 42240 + r0 * 528 + cc * 2) = l01;
            *(__nv_bfloat162*)(smc + (r0 + 8) * 528 + cc * 2) = h23;
            *(__nv_bfloat162*)(smc + 42240 + (r0 + 8) * 528 + cc * 2) = l23;
        }
    }
#pragma unroll
    for (int mi = 0; mi < 3; mi++)
#pragma unroll
        for (int ni = 0; ni < 4; ni++)
#pragma unroll
            for (int j = 0; j < 4; j++) c[mi][ni][j] = 0.0f;

    {   // GEMM2: single 64-col chunk (KD=40)
        __syncthreads();
        {
            const uint4* sH = (const uint4*)Whi;
            const uint4* sL = (const uint4*)Wlo;
            for (int i = t; i < 2048; i += 512) {
                int n = i >> 3, j2 = i & 7;
                *(uint4*)(smc + 118272 + n * 144 + j2 * 16) = sH[i];
                *(uint4*)(smc + 155136 + n * 144 + j2 * 16) = sL[i];
            }
        }
        __syncthreads();
#pragma unroll
        for (int s = 0; s < 4; s++) {
            uint32_t ah[3][4], al[3][4];
#pragma unroll
            for (int mi = 0; mi < 3; mi++) {
                if (mi >= nmi) continue;
                uint32_t off = (uint32_t)(wm * 48 + mi * 16 + (lid & 7) + ((lid >> 3) & 1) * 8) * 528
                             + s * 32 + ((lid >> 4) & 1) * 16;
                ldsm4(ah[mi], uU_hi + off);
                ldsm4(al[mi], uU_lo + off);
            }
#pragma unroll
            for (int np = 0; np < 2; np++) {
                uint32_t off = (uint32_t)(wn * 32 + np * 16 + (lid & 7) + ((lid >> 4) & 1) * 8) * 144
                             + s * 32 + ((lid >> 3) & 1) * 16;
                uint32_t bh[4], bl[4];
                ldsm4(bh, uW_hi + off);
                ldsm4(bl, uW_lo + off);
#pragma unroll
                for (int mi = 0; mi < 3; mi++) {
                    if (mi >= nmi) continue;
                    mma16816(c[mi][np * 2],     ah[mi], bh);
                    mma16816(c[mi][np * 2 + 1], ah[mi], bh + 2);
                    mma16816(c[mi][np * 2],     ah[mi], bl);
                    mma16816(c[mi][np * 2 + 1], ah[mi], bl + 2);
                    mma16816(c[mi][np * 2],     al[mi], bh);
                    mma16816(c[mi][np * 2 + 1], al[mi], bh + 2);
                }
            }
        }
    }

    const float inv = 0.99999500003749973f;
#pragma unroll
    for (int mi = 0; mi < 3; mi++) {
        if (mi >= nmi) continue;
        int r0 = wm * 48 + mi * 16 + (lid >> 2);
#pragma unroll
        for (int half = 0; half < 2; half++) {
            int r = r0 + half * 8;
            if (r >= 66) continue;
#pragma unroll
            for (int ni = 0; ni < 4; ni++) {
                int cc = wn * 32 + ni * 8 + (lid & 3) * 2;
                size_t idx = (size_t)b * 16896 + r * 256 + cc;
                float2 gv = *(const float2*)(g + r * 256 + cc);
                float2 bev = *(const float2*)(be + r * 256 + cc);
                float2 bv2 = *(const float2*)&bs[cc];
                float z0 = tanhf((c[mi][ni][half * 2] + bv2.x) * inv * gv.x + bev.x);
                float z1 = tanhf((c[mi][ni][half * 2 + 1] + bv2.y) * inv * gv.y + bev.y);
                *(float2*)(Out + idx) = make_float2(z0, z1);
            }
        }
    }
}

// ---- fused residual PAIR, M=80 ----
// smem: A@0(14080)/14080  YT@28160(45056)/73216 -> 118272
//       U@118272(42240)/160512 -> 202752   W@0(36864)/36864 (alias dead A/YT)
#define SM_P 202752
__global__ __launch_bounds__(512, 1) void k_tpair(
    const float* __restrict__ Yin,
    const __nv_bfloat16* __restrict__ whiB, const __nv_bfloat16* __restrict__ wloB,
    const __nv_bfloat16* __restrict__ ahiB, const __nv_bfloat16* __restrict__ aloB,
    const float* __restrict__ bB, const float* __restrict__ gB,
    const float* __restrict__ beB, int li, float* __restrict__ Out)
{
    extern __shared__ float sm[];
    char* smc = (char*)sm;
    const int t = threadIdx.x, b = blockIdx.x;
    const int wid = t >> 5, lid = t & 31;
    const int wm = wid >> 3, wn = wid & 7;
    const int nmi = 3 - wm;
    const uint32_t base = smem_u32(smc);
    const uint32_t uA_hi = base, uA_lo = base + 14080;
    const uint32_t uYT_hi = base + 28160, uYT_lo = base + 73216;
    const uint32_t uU_hi = base + 118272, uU_lo = base + 160512;
    const uint32_t uW_hi = base, uW_lo = base + 36864;
    const float inv = 0.99999500003749973f;

    // phase 0: YT pad-zero + convert pair-input Y -> YT hi/lo
    for (int i = t; i < 256 * 7; i += 512) {
        int r = i / 7, w = i - r * 7;
        *(uint32_t*)(smc + 28160 + r * 176 + 132 + w * 4) = 0;
        *(uint32_t*)(smc + 73216 + r * 176 + 132 + w * 4) = 0;
    }
    for (int i = t; i < 66 * 256; i += 512) {
        int m = i >> 8, j = i & 255;
        float a = Yin[(size_t)b * 16896 + i];
        __nv_bfloat16 h = __float2bfloat16(a);
        __nv_bfloat16 l = __float2bfloat16(a - __bfloat162float(h));
        *(__nv_bfloat16*)(smc + 28160 + j * 176 + m * 2) = h;
        *(__nv_bfloat16*)(smc + 73216 + j * 176 + m * 2) = l;
    }

    float c[3][4][4];
    for (int sub = 0; sub < 2; sub++) {
        const int L = li + sub;
        const __nv_bfloat16* Ahi = ahiB + (size_t)(1 + L) * 7040;
        const __nv_bfloat16* Alo = aloB + (size_t)(1 + L) * 7040;
        const __nv_bfloat16* Whi = whiB + (size_t)(1 + L) * 65536;
        const __nv_bfloat16* Wlo = wloB + (size_t)(1 + L) * 65536;
        const float* bb  = bB + (size_t)L * 256;
        const float* gg  = gB + (size_t)L * 16896;
        const float* bbe = beB + (size_t)L * 16896;

        {
            const uint4* sH = (const uint4*)Ahi;
            const uint4* sL = (const uint4*)Alo;
            for (int i = t; i < 880; i += 512) {
                ((uint4*)smc)[i] = sH[i];
                ((uint4*)(smc + 14080))[i] = sL[i];
            }
        }
        __syncthreads();

#pragma unroll
        for (int mi = 0; mi < 3; mi++)
#pragma unroll
            for (int ni = 0; ni < 4; ni++)
#pragma unroll
                for (int j = 0; j < 4; j++) c[mi][ni][j] = 0.0f;

        // GEMM1: U = A @ Y^T
#pragma unroll
        for (int s = 0; s < 5; s++) {
            uint32_t ah[3][4], al[3][4];
#pragma unroll
            for (int mi = 0; mi < 3; mi++) {
                if (mi >= nmi) continue;
                uint32_t off = (uint32_t)(wm * 48 + mi * 16 + (lid & 7) + ((lid >> 3) & 1) * 8) * 176
                             + s * 32 + ((lid >> 4) & 1) * 16;
                ldsm4(ah[mi], uA_hi + off);
                ldsm4(al[mi], uA_lo + off);
            }
#pragma unroll
            for (int np = 0; np < 2; np++) {
                uint32_t off = (uint32_t)(wn * 32 + np * 16 + (lid & 7) + ((lid >> 4) & 1) * 8) * 176
                             + s * 32 + ((lid >> 3) & 1) * 16;
                uint32_t bh[4], bl[4];
                ldsm4(bh, uYT_hi + off);
                ldsm4(bl, uYT_lo + off);
#pragma unroll
                for (int mi = 0; mi < 3; mi++) {
                    if (mi >= nmi) continue;
                    mma16816(c[mi][np * 2],     ah[mi], bh);
                    mma16816(c[mi][np * 2 + 1], ah[mi], bh + 2);
                    mma16816(c[mi][np * 2],     ah[mi], bl);
                    mma16816(c[mi][np * 2 + 1], ah[mi], bl + 2);
                    mma16816(c[mi][np * 2],     al[mi], bh);
                    mma16816(c[mi][np * 2 + 1], al[mi], bh + 2);
                }
            }
        }
        __syncthreads();

        // store U hi/lo (disjoint from A/YT)
#pragma unroll
        for (int mi = 0; mi < 3; mi++) {
            if (mi >= nmi) continue;
            int r0 = wm * 48 + mi * 16 + (lid >> 2);
#pragma unroll
            for (int ni = 0; ni < 4; ni++) {
                int cc = wn * 32 + ni * 8 + (lid & 3) * 2;
                float v0 = c[mi][ni][0], v1 = c[mi][ni][1];
                float v2 = c[mi][ni][2], v3 = c[mi][ni][3];
                __nv_bfloat162 h01 = __floats2bfloat162_rn(v0, v1);
                __nv_bfloat162 l01 = __floats2bfloat162_rn(v0 - __bfloat162float(h01.x),
                                                           v1 - __bfloat162float(h01.y));
                __nv_bfloat162 h23 = __floats2bfloat162_rn(v2, v3);
                __nv_bfloat162 l23 = __floats2bfloat162_rn(v2 - __bfloat162float(h23.x),
                                                           v3 - __bfloat162float(h23.y));
                *(__nv_bfloat162*)(smc + 118272 + r0 * 528 + cc * 2) = h01;
                *(__nv_bfloat162*)(smc + 160512 + r0 * 528 + cc * 2) = l01;
                *(__nv_bfloat162*)(smc + 118272 + (r0 + 8) * 528 + cc * 2) = h23;
                *(__nv_bfloat162*)(smc + 160512 + (r0 + 8) * 528 + cc * 2) = l23;
            }
        }
#pragma unroll
        for (int mi = 0; mi < 3; mi++)
#pragma unroll
            for (int ni = 0; ni < 4; ni++)
#pragma unroll
                for (int j = 0; j < 4; j++) c[mi][ni][j] = 0.0f;

        // GEMM2: T = U @ W^T
        for (int kc = 0; kc < 4; kc++) {
            __syncthreads();
            {
                const uint4* sH = (const uint4*)(Whi + kc * 16384);
                const uint4* sL = (const uint4*)(Wlo + kc * 16384);
                for (int i = t; i < 2048; i += 512) {
                    int n = i >> 3, j2 = i & 7;
                    *(uint4*)(smc + n * 144 + j2 * 16) = sH[i];
                    *(uint4*)(smc + 36864 + n * 144 + j2 * 16) = sL[i];
                }
            }
            __syncthreads();
#pragma unroll
            for (int s = 0; s < 4; s++) {
                uint32_t ah[3][4], al[3][4];
#pragma unroll
                for (int mi = 0; mi < 3; mi++) {
                    if (mi >= nmi) continue;
                    uint32_t off = (uint32_t)(wm * 48 + mi * 16 + (lid & 7) + ((lid >> 3) & 1) * 8) * 528
                                 + kc * 128 + s * 32 + ((lid >> 4) & 1) * 16;
                    ldsm4(ah[mi], uU_hi + off);
                    ldsm4(al[mi], uU_lo + off);
                }
#pragma unroll
                for (int np = 0; np < 2; np++) {
                    uint32_t off = (uint32_t)(wn * 32 + np * 16 + (lid & 7) + ((lid >> 4) & 1) * 8) * 144
                                 + s * 32 + ((lid >> 3) & 1) * 16;
                    uint32_t bh[4], bl[4];
                    ldsm4(bh, uW_hi + off);
                    ldsm4(bl, uW_lo + off);
#pragma unroll
                    for (int mi = 0; mi < 3; mi++) {
                        if (mi >= nmi) continue;
                        mma16816(c[mi][np * 2],     ah[mi], bh);
                        mma16816(c[mi][np * 2 + 1], ah[mi], bh + 2);
                        mma16816(c[mi][np * 2],     ah[mi], bl);
                        mma16816(c[mi][np * 2 + 1], ah[mi], bl + 2);
                        mma16816(c[mi][np * 2],     al[mi], bh);
                        mma16816(c[mi][np * 2 + 1], al[mi], bh + 2);
                    }
                }
            }
        }
        __syncthreads();   // W reads done

        if (sub == 0) {
            // mid epilogue: y1 -> YT hi/lo (transposed)
#pragma unroll
            for (int mi = 0; mi < 3; mi++) {
                if (mi >= nmi) continue;
                int r0 = wm * 48 + mi * 16 + (lid >> 2);
#pragma unroll
                for (int half = 0; half < 2; half++) {
                    int r = r0 + half * 8;
                    if (r >= 66) continue;
#pragma unroll
                    for (int ni = 0; ni < 4; ni++) {
                        int cc = wn * 32 + ni * 8 + (lid & 3) * 2;
                        float2 gv = *(const float2*)(gg + r * 256 + cc);
                        float2 bev = *(const float2*)(bbe + r * 256 + cc);
                        float2 bv2 = *(const float2*)(bb + cc);
                        float z0 = tanhf((c[mi][ni][half * 2] + bv2.x) * inv * gv.x + bev.x);
                        float z1 = tanhf((c[mi][ni][half * 2 + 1] + bv2.y) * inv * gv.y + bev.y);
                        __nv_bfloat16 h0 = __float2bfloat16(z0);
                        __nv_bfloat16 l0 = __float2bfloat16(z0 - __bfloat162float(h0));
                        __nv_bfloat16 h1 = __float2bfloat16(z1);
                        __nv_bfloat16 l1 = __float2bfloat16(z1 - __bfloat162float(h1));
                        *(__nv_bfloat16*)(smc + 28160 + cc * 176 + r * 2) = h0;
                        *(__nv_bfloat16*)(smc + 73216 + cc * 176 + r * 2) = l0;
                        *(__nv_bfloat16*)(smc + 28160 + (cc + 1) * 176 + r * 2) = h1;
                        *(__nv_bfloat16*)(smc + 73216 + (cc + 1) * 176 + r * 2) = l1;
                    }
                }
            }
            for (int i = t; i < 256 * 7; i += 512) {
                int r = i / 7, w = i - r * 7;
                *(uint32_t*)(smc + 28160 + r * 176 + 132 + w * 4) = 0;
                *(uint32_t*)(smc + 73216 + r * 176 + 132 + w * 4) = 0;
            }
        } else {
            // final epilogue: + residual -> Out
#pragma unroll
            for (int mi = 0; mi < 3; mi++) {
                if (mi >= nmi) continue;
                int r0 = wm * 48 + mi * 16 + (lid >> 2);
#pragma unroll
                for (int half = 0; half < 2; half++) {
                    int r = r0 + half * 8;
                    if (r >= 66) continue;
#pragma unroll
                    for (int ni = 0; ni < 4; ni++) {
                        int cc = wn * 32 + ni * 8 + (lid & 3) * 2;
                        size_t idx = (size_t)b * 16896 + r * 256 + cc;
                        float2 gv = *(const float2*)(gg + r * 256 + cc);
                        float2 bev = *(const float2*)(bbe + r * 256 + cc);
                        float2 bv2 = *(const float2*)(bb + cc);
                        float z0 = tanhf((c[mi][ni][half * 2] + bv2.x) * inv * gv.x + bev.x);
                        float z1 = tanhf((c[mi][ni][half * 2 + 1] + bv2.y) * inv * gv.y + bev.y);
                        float2 rv = *(const float2*)(Yin + idx);
                        *(float2*)(Out + idx) = make_float2(z0 + rv.x, z1 + rv.y);
                    }
                }
            }
        }
    }
}

__global__ __launch_bounds__(256, 1) void k_gout(
    const float* __restrict__ Y, const float* __restrict__ Gin,
    const float* __restrict__ gw, const float* __restrict__ gatt,
    const float* __restrict__ gb, float* __restrict__ out)
{
    int b = blockIdx.x;
    extern __shared__ float sm[];
    float* Ys = sm;
    float* gws = Ys + 16964;
    float* As = gws + 5120;
    float* T2 = As + 4356;
    float* Z2 = T2 + 1320;
    float* ds = Z2 + 1320;
    float* bsm = ds + 400;
    int t = threadIdx.x;
    for (int i = t; i < 16896; i += 256) {
        int r = i >> 8, c = i & 255;
        Ys[r * 257 + c] = Y[(size_t)b * 16896 + i];
    }
    for (int i = t; i < 5120; i += 256) {
        int k = i / 20, l = i - k * 20;
        gws[i] = gw[k * 40 + l];
    }
    for (int i = t; i < 4356; i += 256) As[i] = gatt[i];
    for (int i = t; i < 400; i += 256) ds[i] = g_dct[i];
    if (t < 20) bsm[t] = gb[t];
    __syncthreads();
    for (int i = t; i < 1320; i += 256) {
        int m = i / 20, l = i - m * 20;
        float a = 0.0f;
        for (int k = 0; k < 256; k++) a += Ys[m * 257 + k] * gws[k * 20 + l];
        T2[i] = a;
    }
    __syncthreads();
    for (int i = t; i < 1320; i += 256) {
        int n = i / 20, l = i - n * 20;
        float a = bsm[l];
        for (int m = 0; m < 66; m++) a += As[n * 66 + m] * T2[m * 20 + l];
        Z2[i] = a + Gin[(size_t)b * 2640 + n * 40 + l];
    }
    __syncthreads();
    for (int i = t; i < 1320; i += 256) {
        int n = i / 20, m = i - n * 20;
        float a = 0.0f;
#pragma unroll
        for (int l = 0; l < 20; l++) a += Z2[n * 20 + l] * ds[m * 20 + l];
        out[(size_t)b * 1320 + i] = a;
    }
}

extern "C" void kernel_launch(void* const* d_in, const int* in_sizes, int n_in,
                              void* d_out, int out_size)
{
    const float* x        = (const float*)d_in[0];
    const float* q_w1     = (const float*)d_in[1];
    const float* q_b1     = (const float*)d_in[2];
    const float* q_w2     = (const float*)d_in[3];
    const float* q_b2     = (const float*)d_in[4];
    const float* k_w1     = (const float*)d_in[5];
    const float* k_b1     = (const float*)d_in[6];
    const float* k_w2     = (const float*)d_in[7];
    const float* k_b2     = (const float*)d_in[8];
    const float* gin_w    = (const float*)d_in[9];
    const float* gin_att  = (const float*)d_in[10];
    const float* gin_b    = (const float*)d_in[11];
    const float* bn_in_g  = (const float*)d_in[12];
    const float* bn_in_b  = (const float*)d_in[13];
    const float* blk_w    = (const float*)d_in[14];
    const float* blk_att  = (const float*)d_in[15];
    const float* blk_b    = (const float*)d_in[16];
    const float* blk_bn_g = (const float*)d_in[17];
    const float* blk_bn_b = (const float*)d_in[18];
    const float* gout_w   = (const float*)d_in[19];
    const float* gout_att = (const float*)d_in[20];
    const float* gout_b   = (const float*)d_in[21];
    float* out = (float*)d_out;

    int B = in_sizes[0] / 3300;
    if (B > B_MAX) B = B_MAX;
    if (B <= 0) return;

    float *ginp, *b0;
    __nv_bfloat16 *whi, *wlo, *ahi, *alo;
    cudaGetSymbolAddress((void**)&ginp, g_ginp);
    cudaGetSymbolAddress((void**)&b0,   g_buf0);
    cudaGetSymbolAddress((void**)&whi,  g_whi);
    cudaGetSymbolAddress((void**)&wlo,  g_wlo);
    cudaGetSymbolAddress((void**)&ahi,  g_ahi);
    cudaGetSymbolAddress((void**)&alo,  g_alo);

    const int SM_GOUT = 118000;

    cudaFuncSetAttribute((const void*)k_front,
                         cudaFuncAttributeMaxDynamicSharedMemorySize, SM_F);
    cudaFuncSetAttribute((const void*)k_tlayer40,
                         cudaFuncAttributeMaxDynamicSharedMemorySize, SM_T);
    cudaFuncSetAttribute((const void*)k_tpair,
                         cudaFuncAttributeMaxDynamicSharedMemorySize, SM_P);
    cudaFuncSetAttribute((const void*)k_gout,
                         cudaFuncAttributeMaxDynamicSharedMemorySize, SM_GOUT);

    k_prep<<<1024, 256>>>(q_w1, k_w1, q_w2, k_w2, gin_w, blk_w, gin_att, blk_att);
    k_front<<<B, 512, SM_F>>>(x, q_b1, k_b1, q_b2, k_b2, ginp);

    k_tlayer40<<<B, 512, SM_T>>>(ginp, whi, wlo, ahi, alo, gin_b,
                                 bn_in_g, bn_in_b, b0);
    for (int i = 0; i < 12; i += 2)
        k_tpair<<<B, 512, SM_P>>>(b0, whi, wlo, ahi, alo,
                                  blk_b, blk_bn_g, blk_bn_b, i, b0);

    k_gout<<<B, 256, SM_GOUT>>>(b0, ginp, gout_w, gout_att, gout_b, out);
}

// round 17
// speedup vs baseline: 1.0430x; 1.0430x over previous
#include <cuda_runtime.h>
#include <cuda_bf16.h>
#include <math.h>
#include <stdint.h>

#define B_MAX 2048
// IN_N=50 OUT_N=10 KER=10 FEAT=66 HID=256 VLEN=20 VSEQ=31 IF=40 NBLK=12

__device__ float g_ginp[B_MAX * 66 * 40];
__device__ float g_buf0[B_MAX * 66 * 256];
__device__ float g_w1qT[416 * 256];
__device__ float g_w2qT[1280 * 256];
__device__ float g_w1kT[416 * 256];
__device__ float g_w2kT[1280 * 256];
__device__ float g_dct [400];
__device__ __nv_bfloat16 g_whi[13 * 65536];
__device__ __nv_bfloat16 g_wlo[13 * 65536];
__device__ __nv_bfloat16 g_ahi[13 * 8448];
__device__ __nv_bfloat16 g_alo[13 * 8448];

// ---- packed f32x2 helpers (SASS FFMA2) ----
__device__ __forceinline__ void fma2(unsigned long long& c, unsigned long long a,
                                     unsigned long long b) {
    asm("fma.rn.f32x2 %0, %1, %2, %0;" : "+l"(c) : "l"(a), "l"(b));
}
__device__ __forceinline__ unsigned long long pack2(float x, float y) {
    unsigned long long r;
    asm("mov.b64 %0, {%1, %2};" : "=l"(r) : "f"(x), "f"(y));
    return r;
}
__device__ __forceinline__ float2 unpack2(unsigned long long v) {
    float2 r;
    asm("mov.b64 {%0, %1}, %2;" : "=f"(r.x), "=f"(r.y) : "l"(v));
    return r;
}

// ---- mma.sync helpers ----
__device__ __forceinline__ uint32_t smem_u32(const void* p) {
    uint32_t a;
    asm("{ .reg .u64 t; cvta.to.shared.u64 t, %1; cvt.u32.u64 %0, t; }"
        : "=r"(a) : "l"(p));
    return a;
}
__device__ __forceinline__ void ldsm4(uint32_t* r, uint32_t addr) {
    asm volatile("ldmatrix.sync.aligned.m8n8.x4.shared.b16 {%0,%1,%2,%3}, [%4];"
                 : "=r"(r[0]), "=r"(r[1]), "=r"(r[2]), "=r"(r[3]) : "r"(addr));
}
__device__ __forceinline__ void mma16816(float* d, const uint32_t* a, const uint32_t* b) {
    asm volatile(
        "mma.sync.aligned.m16n8k16.row.col.f32.bf16.bf16.f32 "
        "{%0,%1,%2,%3}, {%4,%5,%6,%7}, {%8,%9}, {%0,%1,%2,%3};"
        : "+f"(d[0]), "+f"(d[1]), "+f"(d[2]), "+f"(d[3])
        : "r"(a[0]), "r"(a[1]), "r"(a[2]), "r"(a[3]), "r"(b[0]), "r"(b[1]));
}

// ---- all setup in one kernel ----
__global__ void k_prep(const float* __restrict__ q_w1, const float* __restrict__ k_w1,
                       const float* __restrict__ q_w2, const float* __restrict__ k_w2,
                       const float* __restrict__ gin_w, const float* __restrict__ blk_w,
                       const float* __restrict__ gin_att, const float* __restrict__ blk_att)
{
    int gid = blockIdx.x * blockDim.x + threadIdx.x;
    int GS = gridDim.x * blockDim.x;
    for (int t = gid; t < 400; t += GS) {
        int k = t / 20, i = t % 20;
        float w = (k == 0) ? sqrtf(1.0f / 20.0f) : sqrtf(2.0f / 20.0f);
        g_dct[t] = w * cospif((i + 0.5f) * (float)k / 20.0f);
    }
    for (int i = gid; i < 416 * 256; i += GS) {
        int k = i >> 8, h = i & 255;
        float vq = 0.0f, vk = 0.0f;
        if (k < 396) {
            int l = k / 66, f = k - l * 66;
            vq = q_w1[h * 396 + f * 6 + l];
            vk = k_w1[h * 396 + f * 6 + l];
        }
        g_w1qT[i] = vq; g_w1kT[i] = vk;
    }
    for (int i = gid; i < 1280 * 256; i += GS) {
        int k = i >> 8, h = i & 255, l = k >> 8, c = k & 255;
        g_w2qT[i] = q_w2[h * 1280 + c * 5 + l];
        g_w2kT[i] = k_w2[h * 1280 + c * 5 + l];
    }
    for (int idx = gid; idx < 13 * 65536; idx += GS) {
        int l = idx >> 16, r = idx & 65535;
        int kc = r >> 14, rem = r & 16383;
        int n = rem >> 6, kk = rem & 63;
        int k = kc * 64 + kk;
        float a;
        if (l == 0) a = (k < 40) ? gin_w[k * 256 + n] : 0.0f;
        else        a = blk_w[(size_t)(l - 1) * 65536 + k * 256 + n];
        __nv_bfloat16 h = __float2bfloat16(a);
        g_whi[idx] = h;
        g_wlo[idx] = __float2bfloat16(a - __bfloat162float(h));
    }
    for (int idx = gid; idx < 13 * 8448; idx += GS) {
        int l = idx / 8448, r = idx - l * 8448;
        int n = r / 88, m = r - n * 88;
        float a = 0.0f;
        if (n < 66 && m < 66)
            a = (l == 0) ? gin_att[n * 66 + m]
                         : blk_att[(size_t)(l - 1) * 4356 + n * 66 + m];
        __nv_bfloat16 h = __float2bfloat16(a);
        g_ahi[idx] = h;
        g_alo[idx] = __float2bfloat16(a - __bfloat162float(h));
    }
}

// ---- mega front-end (unchanged) ----
#define FS_H1   3776
#define FS_WTK  14176
#define FS_WTQ  22368
#define FS_OUT2 30560
#define SM_F    (38784 * 4)
__global__ __launch_bounds__(512, 1) void k_front(
    const float* __restrict__ x,
    const float* __restrict__ b1q, const float* __restrict__ b1k,
    const float* __restrict__ b2q, const float* __restrict__ b2k,
    float* __restrict__ ginp)
{
    extern __shared__ float sm[];
    float* xs = sm;
    float* ds = sm + 3300;
    float* sc = sm + 3700;
    float* asw = sm + 3732;
    float* h1 = sm + FS_H1;
    float* wtk = sm + FS_WTK;
    float* wtq = sm + FS_WTQ;
    float* out2 = sm + FS_OUT2;
    const int t = threadIdx.x, b = blockIdx.x;
    const int wid = t >> 5, lane = t & 31;
    const int mg = t & 7, h0 = (t >> 3) * 4;

    for (int i = t; i < 3300; i += 512) xs[i] = x[(size_t)b * 3300 + i];
    for (int i = t; i < 400; i += 512) ds[i] = g_dct[i];

    {   // conv1 q (5 rows)
        unsigned long long acc[2] = {0ULL, 0ULL};
        for (int nt = 0; nt < 13; nt++) {
            __syncthreads();
            for (int i = t; i < 8192; i += 512) wtk[i] = g_w1qT[nt * 8192 + i];
            __syncthreads();
#pragma unroll 4
            for (int kk = 0; kk < 32; kk++) {
                int kc = min(nt * 32 + kk, 395);
                int l = kc / 66, c = kc - l * 66;
                float4 w4 = *(const float4*)&wtk[kk * 256 + h0];
                unsigned long long wlo = pack2(w4.x, w4.y), whi = pack2(w4.z, w4.w);
                if (mg < 5) {
                    float y = xs[(40 + mg + l) * 66 + c];
                    unsigned long long yy = pack2(y, y);
                    fma2(acc[0], yy, wlo);
                    fma2(acc[1], yy, whi);
                }
            }
        }
        if (mg < 5) {
            float4 bv = *(const float4*)&b1q[h0];
            float2 lo = unpack2(acc[0]), hi = unpack2(acc[1]);
            float* hr = &h1[mg * 260 + h0];
            hr[0] = fmaxf(lo.x + bv.x, 0.0f); hr[1] = fmaxf(lo.y + bv.y, 0.0f);
            hr[2] = fmaxf(hi.x + bv.z, 0.0f); hr[3] = fmaxf(hi.y + bv.w, 0.0f);
        }
    }
    {   // conv1 k (35 rows -> h1 rows 5..39)
        unsigned long long acc[5][2];
#pragma unroll
        for (int i = 0; i < 5; i++) { acc[i][0] = 0ULL; acc[i][1] = 0ULL; }
        for (int nt = 0; nt < 13; nt++) {
            __syncthreads();
            for (int i = t; i < 8192; i += 512) wtk[i] = g_w1kT[nt * 8192 + i];
            __syncthreads();
#pragma unroll 4
            for (int kk = 0; kk < 32; kk++) {
                int kc = min(nt * 32 + kk, 395);
                int l = kc / 66, c = kc - l * 66;
                float4 w4 = *(const float4*)&wtk[kk * 256 + h0];
                unsigned long long wlo = pack2(w4.x, w4.y), whi = pack2(w4.z, w4.w);
#pragma unroll
                for (int i = 0; i < 5; i++) {
                    int p = mg + 8 * i;
                    if (p < 35) {
                        float y = xs[(p + l) * 66 + c];
                        unsigned long long yy = pack2(y, y);
                        fma2(acc[i][0], yy, wlo);
                        fma2(acc[i][1], yy, whi);
                    }
                }
            }
        }
        float4 bv = *(const float4*)&b1k[h0];
#pragma unroll
        for (int i = 0; i < 5; i++) {
            int p = mg + 8 * i;
            if (p < 35) {
                float2 lo = unpack2(acc[i][0]), hi = unpack2(acc[i][1]);
                float* hr = &h1[(5 + p) * 260 + h0];
                hr[0] = fmaxf(lo.x + bv.x, 0.0f); hr[1] = fmaxf(lo.y + bv.y, 0.0f);
                hr[2] = fmaxf(hi.x + bv.z, 0.0f); hr[3] = fmaxf(hi.y + bv.w, 0.0f);
            }
        }
    }
    {   // conv2 (q row 0, k rows 1..31 of out2)
        unsigned long long acck[4][2], accq[2] = {0ULL, 0ULL};
#pragma unroll
        for (int i = 0; i < 4; i++) { acck[i][0] = 0ULL; acck[i][1] = 0ULL; }
        for (int nt = 0; nt < 40; nt++) {
            __syncthreads();
            for (int i = t; i < 8192; i += 512) {
                wtk[i] = g_w2kT[nt * 8192 + i];
                wtq[i] = g_w2qT[nt * 8192 + i];
            }
            __syncthreads();
#pragma unroll 4
            for (int kk = 0; kk < 32; kk++) {
                int kc = nt * 32 + kk;
                int l = kc >> 8, c = kc & 255;
                float4 w4 = *(const float4*)&wtk[kk * 256 + h0];
                unsigned long long wlo = pack2(w4.x, w4.y), whi = pack2(w4.z, w4.w);
#pragma unroll
                for (int i = 0; i < 4; i++) {
                    int s = mg + 8 * i;
                    if (s < 31) {
                        float y = h1[(5 + s + l) * 260 + c];
                        unsigned long long yy = pack2(y, y);
                        fma2(acck[i][0], yy, wlo);
                        fma2(acck[i][1], yy, whi);
                    }
                }
                if (mg == 0) {
                    float4 wq = *(const float4*)&wtq[kk * 256 + h0];
                    float y = h1[l * 260 + c];
                    unsigned long long yy = pack2(y, y);
                    fma2(accq[0], yy, pack2(wq.x, wq.y));
                    fma2(accq[1], yy, pack2(wq.z, wq.w));
                }
            }
        }
        float4 bv = *(const float4*)&b2k[h0];
#pragma unroll
        for (int i = 0; i < 4; i++) {
            int s = mg + 8 * i;
            if (s < 31) {
                float2 lo = unpack2(acck[i][0]), hi = unpack2(acck[i][1]);
                float* orow = &out2[(1 + s) * 257 + h0];
                orow[0] = fmaxf(lo.x + bv.x, 0.0f); orow[1] = fmaxf(lo.y + bv.y, 0.0f);
                orow[2] = fmaxf(hi.x + bv.z, 0.0f); orow[3] = fmaxf(hi.y + bv.w, 0.0f);
            }
        }
        if (mg == 0) {
            float4 bq = *(const float4*)&b2q[h0];
            float2 lo = unpack2(accq[0]), hi = unpack2(accq[1]);
            float* orow = &out2[h0];
            orow[0] = fmaxf(lo.x + bq.x, 0.0f); orow[1] = fmaxf(lo.y + bq.y, 0.0f);
            orow[2] = fmaxf(hi.x + bq.z, 0.0f); orow[3] = fmaxf(hi.y + bq.w, 0.0f);
        }
    }
    __syncthreads();
    for (int s = wid; s < 31; s += 16) {
        float v = 0.0f;
        for (int j = lane; j < 256; j += 32) v += out2[j] * out2[(1 + s) * 257 + j];
#pragma unroll
        for (int o = 16; o; o >>= 1) v += __shfl_down_sync(0xffffffffu, v, o);
        if (!lane) sc[s] = v;
    }
    __syncthreads();
    if (t < 32) {
        float v = (t < 31) ? sc[t] : 0.0f, tot = v;
#pragma unroll
        for (int o = 16; o; o >>= 1) tot += __shfl_xor_sync(0xffffffffu, tot, o);
        if (t < 31) asw[t] = v / tot;
    }
    __syncthreads();
    if (t < 264) {
        int f2 = t >> 2, mq = t & 3;
        if (f2 < 66) {
            float G[20];
#pragma unroll
            for (int l = 0; l < 20; l++) G[l] = 0.0f;
            for (int s = 0; s < 31; s++) {
                int j = f2 * 31 + s, sj = j / 66, fj = j - sj * 66;
                float a = asw[s];
#pragma unroll
                for (int l = 0; l < 20; l++) G[l] += a * xs[(sj + l) * 66 + fj];
            }
            float xp[20];
#pragma unroll
            for (int l = 0; l < 20; l++) xp[l] = xs[((l < 10) ? (40 + l) : 49) * 66 + f2];
            float* ob = ginp + (size_t)b * 2640 + f2 * 40;
            for (int m = mq * 5; m < mq * 5 + 5; m++) {
                float pq = 0.0f, af = 0.0f;
#pragma unroll
                for (int l = 0; l < 20; l++) {
                    float d = ds[l * 20 + m];
                    pq += xp[l] * d; af += G[l] * d;
                }
                ob[m] = pq; ob[20 + m] = af;
            }
        }
    }
}

// ---- single layer (input layer KD=40), R15 M=96 layout ----
template<int KD, bool RES>
__global__ __launch_bounds__(512, 1) void k_tlayer(
    const float* __restrict__ Yin,
    const __nv_bfloat16* __restrict__ Whi, const __nv_bfloat16* __restrict__ Wlo,
    const __nv_bfloat16* __restrict__ Ahi, const __nv_bfloat16* __restrict__ Alo,
    const float* __restrict__ bias, const float* __restrict__ g,
    const float* __restrict__ be, const float* __restrict__ Res,
    float* __restrict__ Out)
{
    constexpr int NC2 = (KD == 40) ? 1 : 4;
    extern __shared__ float sm[];
    char* smc = (char*)sm;
    float* bs = (float*)(smc + 197632);
    const int t = threadIdx.x, b = blockIdx.x;
    const int wid = t >> 5, lid = t & 31;
    const int wm = wid >> 3, wn = wid & 7;
    const uint32_t uA_hi  = smem_u32(smc);
    const uint32_t uA_lo  = smem_u32(smc + 16896);
    const uint32_t uYT_hi = smem_u32(smc + 33792);
    const uint32_t uYT_lo = smem_u32(smc + 78848);
    const uint32_t uU_hi  = smem_u32(smc);
    const uint32_t uU_lo  = smem_u32(smc + 50688);
    const uint32_t uW_hi  = smem_u32(smc + 123904);
    const uint32_t uW_lo  = smem_u32(smc + 160768);

    if (t < 256) bs[t] = bias[t];
    {
        const uint4* sH = (const uint4*)Ahi;
        const uint4* sL = (const uint4*)Alo;
        uint4* dH = (uint4*)smc;
        uint4* dL = (uint4*)(smc + 16896);
        for (int i = t; i < 1056; i += 512) { dH[i] = sH[i]; dL[i] = sL[i]; }
    }
    if (KD == 40) {
        for (int i = t; i < 22528; i += 512) ((uint32_t*)(smc + 33792))[i] = 0;
    } else {
        for (int i = t; i < 256 * 7; i += 512) {
            int r = i / 7, w = i - r * 7;
            *(uint32_t*)(smc + 33792 + r * 176 + 132 + w * 4) = 0;
            *(uint32_t*)(smc + 78848 + r * 176 + 132 + w * 4) = 0;
        }
    }
    __syncthreads();
    for (int i = t; i < 66 * KD; i += 512) {
        int m = i / KD, j = i - m * KD;
        float a = Yin[(size_t)b * 66 * KD + i];
        __nv_bfloat16 h = __float2bfloat16(a);
        __nv_bfloat16 l = __float2bfloat16(a - __bfloat162float(h));
        *(__nv_bfloat16*)(smc + 33792 + j * 176 + m * 2) = h;
        *(__nv_bfloat16*)(smc + 78848 + j * 176 + m * 2) = l;
    }
    __syncthreads();

    float c[3][4][4];
#pragma unroll
    for (int mi = 0; mi < 3; mi++)
#pragma unroll
        for (int ni = 0; ni < 4; ni++)
#pragma unroll
            for (int j = 0; j < 4; j++) c[mi][ni][j] = 0.0f;

    if (KD != 40 || wn < 2) {
#pragma unroll
        for (int s = 0; s < 5; s++) {
            uint32_t ah[3][4], al[3][4];
#pragma unroll
            for (int mi = 0; mi < 3; mi++) {
                uint32_t off = (uint32_t)(wm * 48 + mi * 16 + (lid & 7) + ((lid >> 3) & 1) * 8) * 176
                             + s * 32 + ((lid >> 4) & 1) * 16;
                ldsm4(ah[mi], uA_hi + off);
                ldsm4(al[mi], uA_lo + off);
            }
#pragma unroll
            for (int np = 0; np < 2; np++) {
                uint32_t off = (uint32_t)(wn * 32 + np * 16 + (lid & 7) + ((lid >> 4) & 1) * 8) * 176
                             + s * 32 + ((lid >> 3) & 1) * 16;
                uint32_t bh[4], bl[4];
                ldsm4(bh, uYT_hi + off);
                ldsm4(bl, uYT_lo + off);
#pragma unroll
                for (int mi = 0; mi < 3; mi++) {
                    mma16816(c[mi][np * 2],     ah[mi], bh);
                    mma16816(c[mi][np * 2 + 1], ah[mi], bh + 2);
                    mma16816(c[mi][np * 2],     ah[mi], bl);
                    mma16816(c[mi][np * 2 + 1], ah[mi], bl + 2);
                    mma16816(c[mi][np * 2],     al[mi], bh);
                    mma16816(c[mi][np * 2 + 1], al[mi], bh + 2);
                }
            }
        }
    }
    __syncthreads();

#pragma unroll
    for (int mi = 0; mi < 3; mi++) {
        int r0 = wm * 48 + mi * 16 + (lid >> 2);
#pragma unroll
        for (int ni = 0; ni < 4; ni++) {
            int cc = wn * 32 + ni * 8 + (lid & 3) * 2;
            float v0 = c[mi][ni][0], v1 = c[mi][ni][1];
            float v2 = c[mi][ni][2], v3 = c[mi][ni][3];
            __nv_bfloat162 h01 = __floats2bfloat162_rn(v0, v1);
            __nv_bfloat162 l01 = __floats2bfloat162_rn(v0 - __bfloat162float(h01.x),
                                                       v1 - __bfloat162float(h01.y));
            __nv_bfloat162 h23 = __floats2bfloat162_rn(v2, v3);
            __nv_bfloat162 l23 = __floats2bfloat162_rn(v2 - __bfloat162float(h23.x),
                                                       v3 - __bfloat162float(h23.y));
            *(__nv_bfloat162*)(smc + r0 * 528 + cc * 2) = h01;
            *(__nv_bfloat162*)(smc + 50688 + r0 * 528 + cc * 2) = l01;
            *(__nv_bfloat162*)(smc + (r0 + 8) * 528 + cc * 2) = h23;
            *(__nv_bfloat162*)(smc + 50688 + (r0 + 8) * 528 + cc * 2) = l23;
        }
    }
#pragma unroll
    for (int mi = 0; mi < 3; mi++)
#pragma unroll
        for (int ni = 0; ni < 4; ni++)
#pragma unroll
            for (int j = 0; j < 4; j++) c[mi][ni][j] = 0.0f;

    for (int kc = 0; kc < NC2; kc++) {
        __syncthreads();
        {
            const uint4* sH = (const uint4*)(Whi + kc * 16384);
            const uint4* sL = (const uint4*)(Wlo + kc * 16384);
            for (int i = t; i < 2048; i += 512) {
                int n = i >> 3, j2 = i & 7;
                *(uint4*)(smc + 123904 + n * 144 + j2 * 16) = sH[i];
                *(uint4*)(smc + 160768 + n * 144 + j2 * 16) = sL[i];
            }
        }
        __syncthreads();
#pragma unroll
        for (int s = 0; s < 4; s++) {
            uint32_t ah[3][4], al[3][4];
#pragma unroll
            for (int mi = 0; mi < 3; mi++) {
                uint32_t off = (uint32_t)(wm * 48 + mi * 16 + (lid & 7) + ((lid >> 3) & 1) * 8) * 528
                             + kc * 128 + s * 32 + ((lid >> 4) & 1) * 16;
                ldsm4(ah[mi], uU_hi + off);
                ldsm4(al[mi], uU_lo + off);
            }
#pragma unroll
            for (int np = 0; np < 2; np++) {
                uint32_t off = (uint32_t)(wn * 32 + np * 16 + (lid & 7) + ((lid >> 4) & 1) * 8) * 144
                             + s * 32 + ((lid >> 3) & 1) * 16;
                uint32_t bh[4], bl[4];
                ldsm4(bh, uW_hi + off);
                ldsm4(bl, uW_lo + off);
#pragma unroll
                for (int mi = 0; mi < 3; mi++) {
                    mma16816(c[mi][np * 2],     ah[mi], bh);
                    mma16816(c[mi][np * 2 + 1], ah[mi], bh + 2);
                    mma16816(c[mi][np * 2],     ah[mi], bl);
                    mma16816(c[mi][np * 2 + 1], ah[mi], bl + 2);
                    mma16816(c[mi][np * 2],     al[mi], bh);
                    mma16816(c[mi][np * 2 + 1], al[mi], bh + 2);
                }
            }
        }
    }

    const float inv = 0.99999500003749973f;
#pragma unroll
    for (int mi = 0; mi < 3; mi++) {
        int r0 = wm * 48 + mi * 16 + (lid >> 2);
#pragma unroll
        for (int half = 0; half < 2; half++) {
            int r = r0 + half * 8;
            if (r >= 66) continue;
#pragma unroll
            for (int ni = 0; ni < 4; ni++) {
                int cc = wn * 32 + ni * 8 + (lid & 3) * 2;
                size_t idx = (size_t)b * 16896 + r * 256 + cc;
                float2 gv = *(const float2*)(g + r * 256 + cc);
                float2 bev = *(const float2*)(be + r * 256 + cc);
                float2 bv2 = *(const float2*)&bs[cc];
                float z0 = tanhf((c[mi][ni][half * 2] + bv2.x) * inv * gv.x + bev.x);
                float z1 = tanhf((c[mi][ni][half * 2 + 1] + bv2.y) * inv * gv.y + bev.y);
                if (RES) {
                    float2 rv = *(const float2*)(Res + idx);
                    z0 += rv.x; z1 += rv.y;
                }
                *(float2*)(Out + idx) = make_float2(z0, z1);
            }
        }
    }
}

// ---- fused residual PAIR (R15 M=96 layout) ----
#define SM_P 225280
__global__ __launch_bounds__(512, 1) void k_tpair(
    const float* __restrict__ Yin,
    const __nv_bfloat16* __restrict__ whiB, const __nv_bfloat16* __restrict__ wloB,
    const __nv_bfloat16* __restrict__ ahiB, const __nv_bfloat16* __restrict__ aloB,
    const float* __restrict__ bB, const float* __restrict__ gB,
    const float* __restrict__ beB, int li, float* __restrict__ Out)
{
    extern __shared__ float sm[];
    char* smc = (char*)sm;
    const int t = threadIdx.x, b = blockIdx.x;
    const int wid = t >> 5, lid = t & 31;
    const int wm = wid >> 3, wn = wid & 7;
    const uint32_t base = smem_u32(smc);
    const uint32_t uA_hi = base, uA_lo = base + 16896;
    const uint32_t uYT_hi = base + 33792, uYT_lo = base + 78848;
    const uint32_t uU_hi = base + 123904, uU_lo = base + 174592;
    const uint32_t uW_hi = base, uW_lo = base + 36864;
    const float inv = 0.99999500003749973f;

    for (int i = t; i < 256 * 7; i += 512) {
        int r = i / 7, w = i - r * 7;
        *(uint32_t*)(smc + 33792 + r * 176 + 132 + w * 4) = 0;
        *(uint32_t*)(smc + 78848 + r * 176 + 132 + w * 4) = 0;
    }
    for (int i = t; i < 66 * 256; i += 512) {
        int m = i >> 8, j = i & 255;
        float a = Yin[(size_t)b * 16896 + i];
        __nv_bfloat16 h = __float2bfloat16(a);
        __nv_bfloat16 l = __float2bfloat16(a - __bfloat162float(h));
        *(__nv_bfloat16*)(smc + 33792 + j * 176 + m * 2) = h;
        *(__nv_bfloat16*)(smc + 78848 + j * 176 + m * 2) = l;
    }

    float c[3][4][4];
    for (int sub = 0; sub < 2; sub++) {
        const int L = li + sub;
        const __nv_bfloat16* Ahi = ahiB + (size_t)(1 + L) * 8448;
        const __nv_bfloat16* Alo = aloB + (size_t)(1 + L) * 8448;
        const __nv_bfloat16* Whi = whiB + (size_t)(1 + L) * 65536;
        const __nv_bfloat16* Wlo = wloB + (size_t)(1 + L) * 65536;
        const float* bb  = bB + (size_t)L * 256;
        const float* gg  = gB + (size_t)L * 16896;
        const float* bbe = beB + (size_t)L * 16896;

        {
            const uint4* sH = (const uint4*)Ahi;
            const uint4* sL = (const uint4*)Alo;
            for (int i = t; i < 1056; i += 512) {
                ((uint4*)smc)[i] = sH[i];
                ((uint4*)(smc + 16896))[i] = sL[i];
            }
        }
        __syncthreads();

#pragma unroll
        for (int mi = 0; mi < 3; mi++)
#pragma unroll
            for (int ni = 0; ni < 4; ni++)
#pragma unroll
                for (int j = 0; j < 4; j++) c[mi][ni][j] = 0.0f;

#pragma unroll
        for (int s = 0; s < 5; s++) {
            uint32_t ah[3][4], al[3][4];
#pragma unroll
            for (int mi = 0; mi < 3; mi++) {
                uint32_t off = (uint32_t)(wm * 48 + mi * 16 + (lid & 7) + ((lid >> 3) & 1) * 8) * 176
                             + s * 32 + ((lid >> 4) & 1) * 16;
                ldsm4(ah[mi], uA_hi + off);
                ldsm4(al[mi], uA_lo + off);
            }
#pragma unroll
            for (int np = 0; np < 2; np++) {
                uint32_t off = (uint32_t)(wn * 32 + np * 16 + (lid & 7) + ((lid >> 4) & 1) * 8) * 176
                             + s * 32 + ((lid >> 3) & 1) * 16;
                uint32_t bh[4], bl[4];
                ldsm4(bh, uYT_hi + off);
                ldsm4(bl, uYT_lo + off);
#pragma unroll
                for (int mi = 0; mi < 3; mi++) {
                    mma16816(c[mi][np * 2],     ah[mi], bh);
                    mma16816(c[mi][np * 2 + 1], ah[mi], bh + 2);
                    mma16816(c[mi][np * 2],     ah[mi], bl);
                    mma16816(c[mi][np * 2 + 1], ah[mi], bl + 2);
                    mma16816(c[mi][np * 2],     al[mi], bh);
                    mma16816(c[mi][np * 2 + 1], al[mi], bh + 2);
                }
            }
        }
        __syncthreads();

#pragma unroll
        for (int mi = 0; mi < 3; mi++) {
            int r0 = wm * 48 + mi * 16 + (lid >> 2);
#pragma unroll
            for (int ni = 0; ni < 4; ni++) {
                int cc = wn * 32 + ni * 8 + (lid & 3) * 2;
                float v0 = c[mi][ni][0], v1 = c[mi][ni][1];
                float v2 = c[mi][ni][2], v3 = c[mi][ni][3];
                __nv_bfloat162 h01 = __floats2bfloat162_rn(v0, v1);
                __nv_bfloat162 l01 = __floats2bfloat162_rn(v0 - __bfloat162float(h01.x),
                                                           v1 - __bfloat162float(h01.y));
                __nv_bfloat162 h23 = __floats2bfloat162_rn(v2, v3);
                __nv_bfloat162 l23 = __floats2bfloat162_rn(v2 - __bfloat162float(h23.x),
                                                           v3 - __bfloat162float(h23.y));
                *(__nv_bfloat162*)(smc + 123904 + r0 * 528 + cc * 2) = h01;
                *(__nv_bfloat162*)(smc + 174592 + r0 * 528 + cc * 2) = l01;
                *(__nv_bfloat162*)(smc + 123904 + (r0 + 8) * 528 + cc * 2) = h23;
                *(__nv_bfloat162*)(smc + 174592 + (r0 + 8) * 528 + cc * 2) = l23;
            }
        }
#pragma unroll
        for (int mi = 0; mi < 3; mi++)
#pragma unroll
            for (int ni = 0; ni < 4; ni++)
#pragma unroll
                for (int j = 0; j < 4; j++) c[mi][ni][j] = 0.0f;

        for (int kc = 0; kc < 4; kc++) {
            __syncthreads();
            {
                const uint4* sH = (const uint4*)(Whi + kc * 16384);
                const uint4* sL = (const uint4*)(Wlo + kc * 16384);
                for (int i = t; i < 2048; i += 512) {
                    int n = i >> 3, j2 = i & 7;
                    *(uint4*)(smc + n * 144 + j2 * 16) = sH[i];
                    *(uint4*)(smc + 36864 + n * 144 + j2 * 16) = sL[i];
                }
            }
            __syncthreads();
#pragma unroll
            for (int s = 0; s < 4; s++) {
                uint32_t ah[3][4], al[3][4];
#pragma unroll
                for (int mi = 0; mi < 3; mi++) {
                    uint32_t off = (uint32_t)(wm * 48 + mi * 16 + (lid & 7) + ((lid >> 3) & 1) * 8) * 528
                                 + kc * 128 + s * 32 + ((lid >> 4) & 1) * 16;
                    ldsm4(ah[mi], uU_hi + off);
                    ldsm4(al[mi], uU_lo + off);
                }
#pragma unroll
                for (int np = 0; np < 2; np++) {
                    uint32_t off = (uint32_t)(wn * 32 + np * 16 + (lid & 7) + ((lid >> 4) & 1) * 8) * 144
                                 + s * 32 + ((lid >> 3) & 1) * 16;
                    uint32_t bh[4], bl[4];
                    ldsm4(bh, uW_hi + off);
                    ldsm4(bl, uW_lo + off);
#pragma unroll
                    for (int mi = 0; mi < 3; mi++) {
                        mma16816(c[mi][np * 2],     ah[mi], bh);
                        mma16816(c[mi][np * 2 + 1], ah[mi], bh + 2);
                        mma16816(c[mi][np * 2],     ah[mi], bl);
                        mma16816(c[mi][np * 2 + 1], ah[mi], bl + 2);
                        mma16816(c[mi][np * 2],     al[mi], bh);
                        mma16816(c[mi][np * 2 + 1], al[mi], bh + 2);
                    }
                }
            }
        }
        __syncthreads();

        if (sub == 0) {
#pragma unroll
            for (int mi = 0; mi < 3; mi++) {
                int r0 = wm * 48 + mi * 16 + (lid >> 2);
#pragma unroll
                for (int half = 0; half < 2; half++) {
                    int r = r0 + half * 8;
                    if (r >= 66) continue;
#pragma unroll
                    for (int ni = 0; ni < 4; ni++) {
                        int cc = wn * 32 + ni * 8 + (lid & 3) * 2;
                        float2 gv = *(const float2*)(gg + r * 256 + cc);
                        float2 bev = *(const float2*)(bbe + r * 256 + cc);
                        float2 bv2 = *(const float2*)(bb + cc);
                        float z0 = tanhf((c[mi][ni][half * 2] + bv2.x) * inv * gv.x + bev.x);
                        float z1 = tanhf((c[mi][ni][half * 2 + 1] + bv2.y) * inv * gv.y + bev.y);
                        __nv_bfloat16 h0 = __float2bfloat16(z0);
                        __nv_bfloat16 l0 = __float2bfloat16(z0 - __bfloat162float(h0));
                        __nv_bfloat16 h1 = __float2bfloat16(z1);
                        __nv_bfloat16 l1 = __float2bfloat16(z1 - __bfloat162float(h1));
                        *(__nv_bfloat16*)(smc + 33792 + cc * 176 + r * 2) = h0;
                        *(__nv_bfloat16*)(smc + 78848 + cc * 176 + r * 2) = l0;
                        *(__nv_bfloat16*)(smc + 33792 + (cc + 1) * 176 + r * 2) = h1;
                        *(__nv_bfloat16*)(smc + 78848 + (cc + 1) * 176 + r * 2) = l1;
                    }
                }
            }
            for (int i = t; i < 256 * 7; i += 512) {
                int r = i / 7, w = i - r * 7;
                *(uint32_t*)(smc + 33792 + r * 176 + 132 + w * 4) = 0;
                *(uint32_t*)(smc + 78848 + r * 176 + 132 + w * 4) = 0;
            }
        } else {
#pragma unroll
            for (int mi = 0; mi < 3; mi++) {
                int r0 = wm * 48 + mi * 16 + (lid >> 2);
#pragma unroll
                for (int half = 0; half < 2; half++) {
                    int r = r0 + half * 8;
                    if (r >= 66) continue;
#pragma unroll
                    for (int ni = 0; ni < 4; ni++) {
                        int cc = wn * 32 + ni * 8 + (lid & 3) * 2;
                        size_t idx = (size_t)b * 16896 + r * 256 + cc;
                        float2 gv = *(const float2*)(gg + r * 256 + cc);
                        float2 bev = *(const float2*)(bbe + r * 256 + cc);
                        float2 bv2 = *(const float2*)(bb + cc);
                        float z0 = tanhf((c[mi][ni][half * 2] + bv2.x) * inv * gv.x + bev.x);
                        float z1 = tanhf((c[mi][ni][half * 2 + 1] + bv2.y) * inv * gv.y + bev.y);
                        float2 rv = *(const float2*)(Yin + idx);
                        *(float2*)(Out + idx) = make_float2(z0 + rv.x, z1 + rv.y);
                    }
                }
            }
        }
    }
}

// ---- gout: occ 2 (As aliased over Ys), FFMA2 column pairs ----
#define SM_GOUT (25144 * 4)
__global__ __launch_bounds__(256, 2) void k_gout(
    const float* __restrict__ Y, const float* __restrict__ Gin,
    const float* __restrict__ gw, const float* __restrict__ gatt,
    const float* __restrict__ gb, float* __restrict__ out)
{
    int b = blockIdx.x;
    extern __shared__ float sm[];
    float* Ys  = sm;            // 66*257 = 16964 (phase 1 only)
    float* As  = sm;            // alias (4356), used after phase 1
    float* gws = sm + 16964;    // 5120
    float* T2  = sm + 22084;    // 1320
    float* Z2  = sm + 23404;    // 1320
    float* ds  = sm + 24724;    // 400
    float* bsm = sm + 25124;    // 20
    int t = threadIdx.x;
    for (int i = t; i < 16896; i += 256) {
        int r = i >> 8, c = i & 255;
        Ys[r * 257 + c] = Y[(size_t)b * 16896 + i];
    }
    for (int i = t; i < 5120; i += 256) {
        int k = i / 20, l = i - k * 20;
        gws[i] = gw[k * 40 + l];
    }
    for (int i = t; i < 400; i += 256) ds[i] = g_dct[i];
    if (t < 20) bsm[t] = gb[t];
    __syncthreads();
    // phase 1: T2[m][2l..2l+1] via FFMA2
    for (int i = t; i < 660; i += 256) {
        int m = i / 10, lp = i - m * 10;
        unsigned long long acc = 0ULL;
        const float* yr = &Ys[m * 257];
        const float* wr = &gws[lp * 2];
#pragma unroll 8
        for (int k = 0; k < 256; k++) {
            fma2(acc, pack2(yr[k], yr[k]), pack2(wr[k * 20], wr[k * 20 + 1]));
        }
        float2 v = unpack2(acc);
        T2[m * 20 + lp * 2] = v.x;
        T2[m * 20 + lp * 2 + 1] = v.y;
    }
    __syncthreads();
    // load As over dead Ys
    for (int i = t; i < 4356; i += 256) As[i] = gatt[i];
    __syncthreads();
    // phase 2: Z2 via FFMA2 pairs
    for (int i = t; i < 660; i += 256) {
        int n = i / 10, lp = i - n * 10;
        unsigned long long acc = 0ULL;
        const float* ar = &As[n * 66];
        const float* tr = &T2[lp * 2];
#pragma unroll 6
        for (int m = 0; m < 66; m++) {
            fma2(acc, pack2(ar[m], ar[m]), pack2(tr[m * 20], tr[m * 20 + 1]));
        }
        float2 v = unpack2(acc);
        const float* gin = Gin + (size_t)b * 2640 + n * 40;
        Z2[n * 20 + lp * 2]     = v.x + bsm[lp * 2]     + gin[lp * 2];
        Z2[n * 20 + lp * 2 + 1] = v.y + bsm[lp * 2 + 1] + gin[lp * 2 + 1];
    }
    __syncthreads();
    // phase 3: idct (= dct^T)
    for (int i = t; i < 1320; i += 256) {
        int n = i / 20, m = i - n * 20;
        float a = 0.0f;
#pragma unroll
        for (int l = 0; l < 20; l++) a += Z2[n * 20 + l] * ds[m * 20 + l];
        out[(size_t)b * 1320 + i] = a;
    }
}

extern "C" void kernel_launch(void* const* d_in, const int* in_sizes, int n_in,
                              void* d_out, int out_size)
{
    const float* x        = (const float*)d_in[0];
    const float* q_w1     = (const float*)d_in[1];
    const float* q_b1     = (const float*)d_in[2];
    const float* q_w2     = (const float*)d_in[3];
    const float* q_b2     = (const float*)d_in[4];
    const float* k_w1     = (const float*)d_in[5];
    const float* k_b1     = (const float*)d_in[6];
    const float* k_w2     = (const float*)d_in[7];
    const float* k_b2     = (const float*)d_in[8];
    const float* gin_w    = (const float*)d_in[9];
    const float* gin_att  = (const float*)d_in[10];
    const float* gin_b    = (const float*)d_in[11];
    const float* bn_in_g  = (const float*)d_in[12];
    const float* bn_in_b  = (const float*)d_in[13];
    const float* blk_w    = (const float*)d_in[14];
    const float* blk_att  = (const float*)d_in[15];
    const float* blk_b    = (const float*)d_in[16];
    const float* blk_bn_g = (const float*)d_in[17];
    const float* blk_bn_b = (const float*)d_in[18];
    const float* gout_w   = (const float*)d_in[19];
    const float* gout_att = (const float*)d_in[20];
    const float* gout_b   = (const float*)d_in[21];
    float* out = (float*)d_out;

    int B = in_sizes[0] / 3300;
    if (B > B_MAX) B = B_MAX;
    if (B <= 0) return;

    float *ginp, *b0;
    __nv_bfloat16 *whi, *wlo, *ahi, *alo;
    cudaGetSymbolAddress((void**)&ginp, g_ginp);
    cudaGetSymbolAddress((void**)&b0,   g_buf0);
    cudaGetSymbolAddress((void**)&whi,  g_whi);
    cudaGetSymbolAddress((void**)&wlo,  g_wlo);
    cudaGetSymbolAddress((void**)&ahi,  g_ahi);
    cudaGetSymbolAddress((void**)&alo,  g_alo);

    const int SM_T = 198656;

    cudaFuncSetAttribute((const void*)k_front,
                         cudaFuncAttributeMaxDynamicSharedMemorySize, SM_F);
    cudaFuncSetAttribute((const void*)k_tlayer<40,false>,
                         cudaFuncAttributeMaxDynamicSharedMemorySize, SM_T);
    cudaFuncSetAttribute((const void*)k_tpair,
                         cudaFuncAttributeMaxDynamicSharedMemorySize, SM_P);
    cudaFuncSetAttribute((const void*)k_gout,
                         cudaFuncAttributeMaxDynamicSharedMemorySize, SM_GOUT);

    k_prep<<<1024, 256>>>(q_w1, k_w1, q_w2, k_w2, gin_w, blk_w, gin_att, blk_att);
    k_front<<<B, 512, SM_F>>>(x, q_b1, k_b1, q_b2, k_b2, ginp);

    k_tlayer<40,false><<<B, 512, SM_T>>>(ginp, whi, wlo, ahi, alo, gin_b,
                                         bn_in_g, bn_in_b, nullptr, b0);
    for (int i = 0; i < 12; i += 2)
        k_tpair<<<B, 512, SM_P>>>(b0, whi, wlo, ahi, alo,
                                  blk_b, blk_bn_g, blk_bn_b, i, b0);

    k_gout<<<B, 256, SM_GOUT>>>(b0, ginp, gout_w, gout_att, gout_b, out);
}